// round 7
// baseline (speedup 1.0000x reference)
#include <cuda_runtime.h>
#include <cstdint>

// SphConv, tf32 mma.sync, l-group-clustered fused (b,k) columns.
// out[b,o,k] = (scale_l/128) * sum_i x[b,i,k] * w[o,i,l(k)/2]
// Per CTA: 2 batches. Columns grouped by lg -> 144 padded m-rows (16,16,32,32,48).
// GEMM view: D[m=(b,k), n=o] = Xg[m, i] * Wlg^T[i, o], K=128 (i), lg fixed per m-block.
// Weights are the B operand, register-resident per warp per lg (read ONCE per CTA).

#define NCOEF 45
#define BSTRIDE (128 * NCOEF)
#define XROW 132                       // floats per smem row (128 + 4 pad)
#define NROWS 144
#define SMEM_BYTES (NROWS * XROW * 4)  // 76032

// B fragments: g_wpB[((lg*16 + nb)*8 + ks2)*32 + lane] =
//   { b0(2ks2), b1(2ks2), b0(2ks2+1), b1(2ks2+1) },  b0(ks)=W[o][ks*8+lc]*s (tf32),
//   b1(ks)=W[o][ks*8+lc+4]*s,  o = nb*8 + (lane>>2), lc = lane&3.
__device__ float4 g_wpB[5 * 16 * 8 * 32];
__device__ int g_gcolAddr[90];         // (b_l*45 + k) -> grouped_row * XROW

__global__ void prep_w(const float* __restrict__ w) {
    int idx  = blockIdx.x * blockDim.x + threadIdx.x;   // 20480 exactly
    int lane = idx & 31;
    int ks2  = (idx >> 5) & 7;
    int nb   = (idx >> 8) & 15;
    int lg   = idx >> 12;
    int o    = nb * 8 + (lane >> 2);
    int i0   = ks2 * 16 + (lane & 3);
    float l  = 2.0f * (float)lg;
    float s  = 6.28318530717958647692f *
               sqrtf(12.5663706143591729539f / (2.0f * l + 1.0f)) * (1.0f / 128.0f);
    float4 v;
    v.x = w[(o * 128 + i0) * 5 + lg] * s;
    v.y = w[(o * 128 + i0 + 4) * 5 + lg] * s;
    v.z = w[(o * 128 + i0 + 8) * 5 + lg] * s;
    v.w = w[(o * 128 + i0 + 12) * 5 + lg] * s;
    asm("cvt.rna.tf32.f32 %0, %0;" : "+f"(v.x));
    asm("cvt.rna.tf32.f32 %0, %0;" : "+f"(v.y));
    asm("cvt.rna.tf32.f32 %0, %0;" : "+f"(v.z));
    asm("cvt.rna.tf32.f32 %0, %0;" : "+f"(v.w));
    g_wpB[idx] = v;

    if (idx < 90) {
        int b_l = idx / 45, k = idx % 45;
        int lg2  = (k >= 28) ? 4 : (k >= 15) ? 3 : (k >= 6) ? 2 : (k >= 1) ? 1 : 0;
        int glo  = 2 * lg2 * lg2 - lg2;
        int glen = 4 * lg2 + 1;
        int base = (lg2 == 0) ? 0 : (lg2 == 1) ? 16 : (lg2 == 2) ? 32
                                 : (lg2 == 3) ? 64 : 96;
        g_gcolAddr[idx] = (base + b_l * glen + (k - glo)) * XROW;
    }
}

__device__ __forceinline__ uint32_t smem_u32(const void* p) {
    uint32_t a;
    asm("{ .reg .u64 t; cvta.to.shared.u64 t, %1; cvt.u32.u64 %0, t; }" : "=r"(a) : "l"(p));
    return a;
}
__device__ __forceinline__ void ldsm4(uint32_t* r, uint32_t addr) {
    asm volatile("ldmatrix.sync.aligned.m8n8.x4.shared.b16 {%0,%1,%2,%3}, [%4];"
                 : "=r"(r[0]), "=r"(r[1]), "=r"(r[2]), "=r"(r[3]) : "r"(addr));
}
__device__ __forceinline__ void mma4(float* d, const uint32_t* a,
                                     uint32_t b0, uint32_t b1) {
    asm volatile(
        "mma.sync.aligned.m16n8k8.row.col.f32.tf32.tf32.f32 "
        "{%0,%1,%2,%3}, {%4,%5,%6,%7}, {%8,%9}, {%0,%1,%2,%3};"
        : "+f"(d[0]), "+f"(d[1]), "+f"(d[2]), "+f"(d[3])
        : "r"(a[0]), "r"(a[1]), "r"(a[2]), "r"(a[3]), "r"(b0), "r"(b1));
}

__global__ void __launch_bounds__(256)
sph_g(const float* __restrict__ x, float* __restrict__ out) {
    extern __shared__ __align__(16) float Xs[];   // [144][XROW]
    const int tid = threadIdx.x;

    // ---- fill smem: coalesced LDG, tf32 pre-round, lg-grouped STS ----
    {
        const float* src = x + (size_t)blockIdx.x * 2 * BSTRIDE + tid;
        int k = tid % 45, i = tid / 45, b_l = 0;
        #pragma unroll 1
        for (int t = 0; t < 45; t++) {
            float v = __ldg(src + (size_t)t * 256);
            asm("cvt.rna.tf32.f32 %0, %0;" : "+f"(v));
            Xs[g_gcolAddr[b_l * 45 + k] + i] = v;
            k += 31; i += 5;
            if (k >= 45) { k -= 45; i += 1; }
            if (i >= 128) { i -= 128; b_l = 1; }
        }
    }
    __syncthreads();

    // ---- compute: warp = 16 o-columns (2 n8 blocks), all 9 m-blocks ----
    const int lane = tid & 31, wid = tid >> 5;
    const int lr = lane >> 2, lc = lane & 3;
    const uint32_t sbase = smem_u32(Xs);
    const uint32_t aAddr = sbase + (uint32_t)(((lane & 15) * XROW) * 4
                                              + ((lane >> 4) * 16));
    const int o0 = wid * 16 + lc * 2;

    float4 b4[2][8];                    // register-resident weights for current lg

    #pragma unroll
    for (int mb = 0; mb < 9; mb++) {
        constexpr int LGB[9] = {0, 1, 2, 2, 3, 3, 4, 4, 4};
        const int lg = LGB[mb];

        if (mb == 0 || lg != LGB[mb - 1]) {
            const float4* wp = g_wpB + (size_t)((lg * 16 + wid * 2) * 8) * 32 + lane;
            #pragma unroll
            for (int nb2 = 0; nb2 < 2; nb2++)
                #pragma unroll
                for (int q = 0; q < 8; q++)
                    b4[nb2][q] = wp[(nb2 * 8 + q) * 32];
        }

        float c0[4] = {0, 0, 0, 0}, c1[4] = {0, 0, 0, 0};
        uint32_t a0[4], a1[4];
        const uint32_t ab = aAddr + (uint32_t)(mb * 16 * XROW * 4);
        ldsm4(a0, ab);

        #pragma unroll
        for (int ks = 0; ks < 16; ks++) {
            uint32_t* ac = (ks & 1) ? a1 : a0;
            uint32_t* an = (ks & 1) ? a0 : a1;
            if (ks < 15) ldsm4(an, ab + (uint32_t)((ks + 1) * 32));
            const float4 f0 = b4[0][ks >> 1];
            const float4 f1 = b4[1][ks >> 1];
            uint32_t p00, p01, p10, p11;
            if (ks & 1) {
                p00 = __float_as_uint(f0.z); p01 = __float_as_uint(f0.w);
                p10 = __float_as_uint(f1.z); p11 = __float_as_uint(f1.w);
            } else {
                p00 = __float_as_uint(f0.x); p01 = __float_as_uint(f0.y);
                p10 = __float_as_uint(f1.x); p11 = __float_as_uint(f1.y);
            }
            mma4(c0, ac, p00, p01);
            mma4(c1, ac, p10, p11);
        }

        // ---- epilogue for this m-block (predicated on group padding) ----
        {
            const int glo  = 2 * lg * lg - lg;
            const int glen = 4 * lg + 1;
            const int base = (lg == 0) ? 0 : (lg == 1) ? 16 : (lg == 2) ? 32
                                           : (lg == 3) ? 64 : 96;
            #pragma unroll
            for (int h = 0; h < 2; h++) {
                const int r = mb * 16 + lr + h * 8;
                const int local = r - base;
                if (local < 2 * glen) {
                    const int bl2 = (local >= glen) ? 1 : 0;
                    const int k = glo + local - (bl2 ? glen : 0);
                    float* q = out + (size_t)(blockIdx.x * 2 + bl2) * BSTRIDE + k;
                    q[o0 * 45]            = c0[h * 2];
                    q[o0 * 45 + 45]       = c0[h * 2 + 1];
                    q[(o0 + 8) * 45]      = c1[h * 2];
                    q[(o0 + 8) * 45 + 45] = c1[h * 2 + 1];
                }
            }
        }
    }
}

extern "C" void kernel_launch(void* const* d_in, const int* in_sizes, int n_in,
                              void* d_out, int out_size) {
    const float* x = (const float*)d_in[0];   // [16384, 128, 45] f32
    const float* w = (const float*)d_in[1];   // [128, 128, 5]   f32
    float* out = (float*)d_out;

    cudaFuncSetAttribute(sph_g, cudaFuncAttributeMaxDynamicSharedMemorySize,
                         SMEM_BYTES);

    prep_w<<<80, 256>>>(w);
    sph_g<<<8192, 256, SMEM_BYTES>>>(x, out);
}

// round 8
// speedup vs baseline: 2.4343x; 2.4343x over previous
#include <cuda_runtime.h>
#include <cstdint>

// SphConv, tf32 mma.sync, lg-grouped rows with OVERLAPPING m16 blocks (no padding).
// out[b,o,k] = (scale_l/128) * sum_i x[b,i,k] * w[o,i,l(k)/2]
// CTA = 2 batches: 90 grouped rows (m), n = 128 (o), K = 128 (i).
// Weights = B operand, register-cached per (lg, K-half). Blocks overlap inside an
// lg-group; epilogue predicates give each row exactly one writer.

#define NCOEF 45
#define BSTRIDE (128 * NCOEF)
#define XROW 132                        // floats per row (128 + 4 pad) -> 528B
#define SMEM_FLOATS (90 * XROW)         // 47520 B < 48KB static limit

// B fragments: g_wpB[((lg*16 + nb)*8 + ks2)*32 + lane] =
//  {b0(2ks2), b1(2ks2), b0(2ks2+1), b1(2ks2+1)}; b0(ks)=W[o][ks*8+lc]*s (tf32),
//  b1(ks)=W[o][ks*8+lc+4]*s; o = nb*8 + (lane>>2), lc = lane&3.
__device__ float4 g_wpB[5 * 16 * 8 * 32];

__global__ void prep_w(const float* __restrict__ w) {
    int idx  = blockIdx.x * blockDim.x + threadIdx.x;   // 20480 exactly
    int lane = idx & 31;
    int ks2  = (idx >> 5) & 7;
    int nb   = (idx >> 8) & 15;
    int lg   = idx >> 12;
    int o    = nb * 8 + (lane >> 2);
    int i0   = ks2 * 16 + (lane & 3);
    float l  = 2.0f * (float)lg;
    float s  = 6.28318530717958647692f *
               sqrtf(12.5663706143591729539f / (2.0f * l + 1.0f)) * (1.0f / 128.0f);
    float4 v;
    v.x = w[(o * 128 + i0) * 5 + lg] * s;
    v.y = w[(o * 128 + i0 + 4) * 5 + lg] * s;
    v.z = w[(o * 128 + i0 + 8) * 5 + lg] * s;
    v.w = w[(o * 128 + i0 + 12) * 5 + lg] * s;
    asm("cvt.rna.tf32.f32 %0, %0;" : "+f"(v.x));
    asm("cvt.rna.tf32.f32 %0, %0;" : "+f"(v.y));
    asm("cvt.rna.tf32.f32 %0, %0;" : "+f"(v.z));
    asm("cvt.rna.tf32.f32 %0, %0;" : "+f"(v.w));
    g_wpB[idx] = v;
}

__device__ __forceinline__ uint32_t smem_u32(const void* p) {
    uint32_t a;
    asm("{ .reg .u64 t; cvta.to.shared.u64 t, %1; cvt.u32.u64 %0, t; }" : "=r"(a) : "l"(p));
    return a;
}
__device__ __forceinline__ void ldsm4(uint32_t* r, uint32_t addr) {
    asm volatile("ldmatrix.sync.aligned.m8n8.x4.shared.b16 {%0,%1,%2,%3}, [%4];"
                 : "=r"(r[0]), "=r"(r[1]), "=r"(r[2]), "=r"(r[3]) : "r"(addr));
}
__device__ __forceinline__ void mma4(float* d, const uint32_t* a,
                                     uint32_t b0, uint32_t b1) {
    asm volatile(
        "mma.sync.aligned.m16n8k8.row.col.f32.tf32.tf32.f32 "
        "{%0,%1,%2,%3}, {%4,%5,%6,%7}, {%8,%9}, {%0,%1,%2,%3};"
        : "+f"(d[0]), "+f"(d[1]), "+f"(d[2]), "+f"(d[3])
        : "r"(a[0]), "r"(a[1]), "r"(a[2]), "r"(a[3]), "r"(b0), "r"(b1));
}

// One lg-run: L blocks, bases B0..B2, accumulate over K in 2 halves, then store.
template <int LG, int L, int B0, int B1, int B2>
__device__ __forceinline__ void do_run(uint32_t sA, const float4* wpBase,
                                       float* ob, int lr, int o0) {
    constexpr int BASES[3] = {B0, B1, B2};
    constexpr int GLO = 2 * LG * LG - LG;
    constexpr int GLEN = 4 * LG + 1;
    constexpr int GLO2 = 2 * GLO;
    constexpr int GHI2 = GLO2 + 2 * GLEN;

    const float4* p = wpBase + LG * 4096;

    float acc[L][8];
    #pragma unroll
    for (int j = 0; j < L; j++)
        #pragma unroll
        for (int q = 0; q < 8; q++) acc[j][q] = 0.0f;

    #pragma unroll
    for (int h = 0; h < 2; h++) {
        float4 b4[2][4];
        #pragma unroll
        for (int nb2 = 0; nb2 < 2; nb2++)
            #pragma unroll
            for (int q = 0; q < 4; q++)
                b4[nb2][q] = p[nb2 * 256 + (h * 4 + q) * 32];

        #pragma unroll
        for (int j = 0; j < L; j++) {
            const uint32_t ab = sA + (uint32_t)(BASES[j] * (XROW * 4) + h * 256);
            uint32_t a0[4], a1[4];
            ldsm4(a0, ab);
            #pragma unroll
            for (int ks = 0; ks < 8; ks++) {
                uint32_t* ac = (ks & 1) ? a1 : a0;
                uint32_t* an = (ks & 1) ? a0 : a1;
                if (ks < 7) ldsm4(an, ab + (uint32_t)((ks + 1) * 32));
                const int q = ks >> 1;
                uint32_t w00, w01, w10, w11;
                if (ks & 1) {
                    w00 = __float_as_uint(b4[0][q].z); w01 = __float_as_uint(b4[0][q].w);
                    w10 = __float_as_uint(b4[1][q].z); w11 = __float_as_uint(b4[1][q].w);
                } else {
                    w00 = __float_as_uint(b4[0][q].x); w01 = __float_as_uint(b4[0][q].y);
                    w10 = __float_as_uint(b4[1][q].x); w11 = __float_as_uint(b4[1][q].y);
                }
                mma4(&acc[j][0], ac, w00, w01);
                mma4(&acc[j][4], ac, w10, w11);
            }
        }
    }

    // epilogue: each grouped row written by exactly one block
    #pragma unroll
    for (int j = 0; j < L; j++) {
        const int wlo = (j == 0) ? GLO2 : BASES[j - 1] + 16;
        const int whi = (BASES[j] + 16 < GHI2) ? BASES[j] + 16 : GHI2;
        #pragma unroll
        for (int hh = 0; hh < 2; hh++) {
            const int g = BASES[j] + lr + hh * 8;
            if (g >= wlo && g < whi) {
                const int local = g - GLO2;
                const int b_l = (local >= GLEN) ? 1 : 0;
                const int k = GLO + local - (b_l ? GLEN : 0);
                float* q = ob + (size_t)b_l * BSTRIDE + k;
                q[o0 * NCOEF]       = acc[j][hh * 2];
                q[(o0 + 1) * NCOEF] = acc[j][hh * 2 + 1];
                q[(o0 + 8) * NCOEF] = acc[j][4 + hh * 2];
                q[(o0 + 9) * NCOEF] = acc[j][4 + hh * 2 + 1];
            }
        }
    }
}

__global__ void __launch_bounds__(256, 3)
sph_r8(const float* __restrict__ x, float* __restrict__ out) {
    __shared__ __align__(16) float Xs[SMEM_FLOATS];
    const int tid = threadIdx.x;

    // ---- fill: batched LDG (MLP 16) -> cvt.rna -> grouped STS ----
    {
        const float* src = x + (size_t)blockIdx.x * 2 * BSTRIDE + tid;
        int k = tid % 45, i = tid / 45, b_l = 0;
        int t = 0;
        #pragma unroll
        for (int batch = 0; batch < 3; batch++) {
            const int nb = (batch < 2) ? 16 : 13;
            float v[16];
            #pragma unroll
            for (int u = 0; u < 16; u++)
                if (u < nb) v[u] = __ldg(src + (size_t)(t + u) * 256);
            #pragma unroll
            for (int u = 0; u < 16; u++) {
                if (u < nb) {
                    float val = v[u];
                    asm("cvt.rna.tf32.f32 %0, %0;" : "+f"(val));
                    const int lg = (k >= 28) ? 4 : (k >= 15) ? 3 : (k >= 6) ? 2
                                              : (k >= 1) ? 1 : 0;
                    const int glo = 2 * lg * lg - lg;
                    const int glen = 4 * lg + 1;
                    const int row = 2 * glo + b_l * glen + (k - glo);
                    Xs[row * XROW + i] = val;
                    k += 31; i += 5;
                    if (k >= 45) { k -= 45; i += 1; }
                    if (i >= 128) { i -= 128; b_l = 1; }
                }
            }
            t += nb;
        }
    }
    __syncthreads();

    const int lane = tid & 31, wid = tid >> 5;
    const int lr = lane >> 2, lc = lane & 3;
    const uint32_t sbase = smem_u32(Xs);
    const uint32_t sA = sbase + (uint32_t)(((lane & 15) * XROW) * 4
                                           + ((lane >> 4) * 16));
    const float4* wpBase = g_wpB + wid * 512 + lane;
    float* ob = out + (size_t)blockIdx.x * 2 * BSTRIDE;
    const int o0 = wid * 16 + lc * 2;

    do_run<0, 1, 0,  0,  0>(sA, wpBase, ob, lr, o0);
    do_run<1, 1, 2,  0,  0>(sA, wpBase, ob, lr, o0);
    do_run<2, 2, 12, 14, 0>(sA, wpBase, ob, lr, o0);
    do_run<3, 2, 30, 40, 0>(sA, wpBase, ob, lr, o0);
    do_run<4, 3, 56, 72, 74>(sA, wpBase, ob, lr, o0);
}

extern "C" void kernel_launch(void* const* d_in, const int* in_sizes, int n_in,
                              void* d_out, int out_size) {
    const float* x = (const float*)d_in[0];   // [16384, 128, 45] f32
    const float* w = (const float*)d_in[1];   // [128, 128, 5]   f32
    float* out = (float*)d_out;

    prep_w<<<80, 256>>>(w);
    sph_r8<<<8192, 256>>>(x, out);
}